// round 12
// baseline (speedup 1.0000x reference)
#include <cuda_runtime.h>
#include <cstdint>
#include <cstddef>
#include <cstring>

#define NTIME 20
#define V     128
#define F     128
#define LRELU_ALPHA 0.2f
#define LOG2E 1.4426950408889634f
#define ALOG2E (LRELU_ALPHA * LOG2E)

#define OUT_HP_ELEMS   (NTIME * V * F)
#define ATT_OFF        OUT_HP_ELEMS

__device__ float g_Wh[NTIME * V * F];
__device__ float g_P1[NTIME * V * F];      // exp2(log2e * e1)
__device__ float g_N1[NTIME * V * F];      // exp2(0.2 * log2e * e1)
__device__ float g_PN2[NTIME * V * F * 2]; // interleaved (exp2(l*e2), exp2(0.2l*e2))

__device__ __forceinline__ float ex2(float x) {
    float r; asm("ex2.approx.f32 %0, %1;" : "=f"(r) : "f"(x)); return r;
}

// ----------------------------------------------------------------------------
// Kernel 1 (fused): per block of MT=8 rows:
//   phase 1: Wh = h @ W        -> smem whs + g_Wh
//   phase 2: e1 = Whs @ a1, e2 = Whs @ a2  -> ex2 tables (P1/N1, PN2)
// 256 threads, 4 rows/thread, grid = 320.
// ----------------------------------------------------------------------------
#define MT 8

__global__ void __launch_bounds__(256) gemm_fused(
    const float* __restrict__ h,
    const float* __restrict__ W,
    const float* __restrict__ a)
{
    __shared__ float hs[MT * F];
    __shared__ float whs[MT * F];

    const int tid  = threadIdx.x;
    const int f    = tid & 127;
    const int half = tid >> 7;
    const int m0   = blockIdx.x * MT;

    ((float4*)hs)[tid] = ((const float4*)(h + (size_t)m0 * F))[tid];
    __syncthreads();

    {
        float acc[4] = {0.f, 0.f, 0.f, 0.f};
#pragma unroll 8
        for (int k4 = 0; k4 < F / 4; k4++) {
            float mv[4];
#pragma unroll
            for (int u = 0; u < 4; u++)
                mv[u] = __ldg(W + (k4 * 4 + u) * F + f);
#pragma unroll
            for (int r = 0; r < 4; r++) {
                const float4 hv = ((const float4*)(hs + (half * 4 + r) * F))[k4];
                acc[r] = fmaf(hv.x, mv[0], acc[r]);
                acc[r] = fmaf(hv.y, mv[1], acc[r]);
                acc[r] = fmaf(hv.z, mv[2], acc[r]);
                acc[r] = fmaf(hv.w, mv[3], acc[r]);
            }
        }
#pragma unroll
        for (int r = 0; r < 4; r++) {
            const int row = half * 4 + r;
            whs[row * F + f] = acc[r];
            g_Wh[(size_t)(m0 + row) * F + f] = acc[r];
        }
    }
    __syncthreads();

    {
        float ac1[4] = {0.f, 0.f, 0.f, 0.f};
        float ac2[4] = {0.f, 0.f, 0.f, 0.f};
#pragma unroll 8
        for (int k4 = 0; k4 < F / 4; k4++) {
            float a1v[4], a2v[4];
#pragma unroll
            for (int u = 0; u < 4; u++) {
                a1v[u] = __ldg(a + (k4 * 4 + u) * F + f);
                a2v[u] = __ldg(a + (F + k4 * 4 + u) * F + f);
            }
#pragma unroll
            for (int r = 0; r < 4; r++) {
                const float4 wv = ((const float4*)(whs + (half * 4 + r) * F))[k4];
                ac1[r] = fmaf(wv.x, a1v[0], ac1[r]);
                ac1[r] = fmaf(wv.y, a1v[1], ac1[r]);
                ac1[r] = fmaf(wv.z, a1v[2], ac1[r]);
                ac1[r] = fmaf(wv.w, a1v[3], ac1[r]);
                ac2[r] = fmaf(wv.x, a2v[0], ac2[r]);
                ac2[r] = fmaf(wv.y, a2v[1], ac2[r]);
                ac2[r] = fmaf(wv.z, a2v[2], ac2[r]);
                ac2[r] = fmaf(wv.w, a2v[3], ac2[r]);
            }
        }
#pragma unroll
        for (int r = 0; r < 4; r++) {
            const size_t idx = (size_t)(m0 + half * 4 + r) * F + f;
            g_P1[idx] = ex2(LOG2E  * ac1[r]);
            g_N1[idx] = ex2(ALOG2E * ac1[r]);
            *(float2*)(g_PN2 + idx * 2) =
                make_float2(ex2(LOG2E * ac2[r]), ex2(ALOG2E * ac2[r]));
        }
    }
}

// ----------------------------------------------------------------------------
// Kernel 2: attention. L1-wavefront-optimized:
//  - warp handles TWO i's (i0, i0+1): q/Wh loads amortized across both
//  - p = max(P1*P2, N1*N2)  (valid: v>0 <=> exp(v)>=exp(0.2v); r>0 preserves)
//  - j-split: warp pair (w, w^1) splits j in halves; partials via smem
// Block = 512 thr = 8 i-pairs x 2 jh -> 16 i. Grid = 16 x 20 = 320.
// smem = PN2 tile 64KB + red 16KB = 80KB -> 2 CTA/SM.
// ----------------------------------------------------------------------------
#define FH  64
#define ATTN_SMEM_BYTES ((2 * V * FH + 16 * 32 * 8) * (int)sizeof(float))

__global__ void __launch_bounds__(512, 2) attn_fused(
    const float* __restrict__ adj,
    float* __restrict__ out)
{
    extern __shared__ float sm[];
    float*  pn2 = sm;                          // [V][FH][2]
    float4* red = (float4*)(sm + 2 * V * FH);  // [16 warps][32 lanes][2 i]

    const int t    = blockIdx.y;
    const int bx   = blockIdx.x;      // 0..15
    const int fh   = bx & 1;
    const int ig   = bx >> 1;         // 0..7
    const int tid  = threadIdx.x;
    const int lane = tid & 31;
    const int w    = tid >> 5;        // warp 0..15
    const int pw   = w >> 1;          // i-pair 0..7
    const int jh   = w & 1;           // j-half
    const int i0   = ig * 16 + pw * 2;
    const int i1   = i0 + 1;
    const int f2   = fh * FH + lane * 2;

    // adjacency bits for both i's over this warp's 64 j's
    uint32_t b0[2], b1[2];
    {
        const float* r0 = adj + (size_t)i0 * V + jh * 64;
        const float* r1 = adj + (size_t)i1 * V + jh * 64;
        b0[0] = __ballot_sync(0xFFFFFFFFu, r0[lane]      > 0.0f);
        b0[1] = __ballot_sync(0xFFFFFFFFu, r0[32 + lane] > 0.0f);
        b1[0] = __ballot_sync(0xFFFFFFFFu, r1[lane]      > 0.0f);
        b1[1] = __ballot_sync(0xFFFFFFFFu, r1[32 + lane] > 0.0f);
    }

    // coop load PN2 tile: 4096 float4, 8 per thread
    {
        const float* src = g_PN2 + ((size_t)t * V * F + fh * FH) * 2;
#pragma unroll
        for (int u = 0; u < 8; u++) {
            const int idx = tid + u * 512;
            const int j = idx >> 5, c = idx & 31;
            ((float4*)pn2)[idx] = *(const float4*)(src + (size_t)j * F * 2 + c * 4);
        }
    }

    const float2 p1_0 = *(const float2*)(g_P1 + ((size_t)t * V + i0) * F + f2);
    const float2 n1_0 = *(const float2*)(g_N1 + ((size_t)t * V + i0) * F + f2);
    const float2 p1_1 = *(const float2*)(g_P1 + ((size_t)t * V + i1) * F + f2);
    const float2 n1_1 = *(const float2*)(g_N1 + ((size_t)t * V + i1) * F + f2);
    __syncthreads();

    const float* pnl = pn2 + (jh * 64) * FH * 2 + lane * 4;
    const float* whg = g_Wh + ((size_t)t * V + jh * 64) * F + f2;

    // Pass A: partial sums over own 64 j's for BOTH i's
    float s0_0 = 0.f, s1_0 = 0.f, a0_0 = 0.f, a1_0 = 0.f;
    float s0_1 = 0.f, s1_1 = 0.f, a0_1 = 0.f, a1_1 = 0.f;
#pragma unroll
    for (int ww = 0; ww < 2; ww++) {
        const uint32_t w0 = b0[ww], w1 = b1[ww];
        const uint32_t wa = w0 | w1;
        const float* pnw = pnl + ww * 32 * FH * 2;
        const float* whw = whg + (size_t)ww * 32 * F;
#pragma unroll
        for (int b = 0; b < 32; b++) {
            if (wa & (1u << b)) {
                const float4 q  = *(const float4*)(pnw + b * FH * 2);
                const float2 wv = __ldg((const float2*)(whw + (size_t)b * F));
                if (w0 & (1u << b)) {
                    const float v0 = fmaxf(p1_0.x * q.x, n1_0.x * q.y);
                    const float v1 = fmaxf(p1_0.y * q.z, n1_0.y * q.w);
                    s0_0 += v0;  s1_0 += v1;
                    a0_0 = fmaf(v0, wv.x, a0_0);
                    a1_0 = fmaf(v1, wv.y, a1_0);
                }
                if (w1 & (1u << b)) {
                    const float v0 = fmaxf(p1_1.x * q.x, n1_1.x * q.y);
                    const float v1 = fmaxf(p1_1.y * q.z, n1_1.y * q.w);
                    s0_1 += v0;  s1_1 += v1;
                    a0_1 = fmaf(v0, wv.x, a0_1);
                    a1_1 = fmaf(v1, wv.y, a1_1);
                }
            }
        }
    }

    // exchange partials with partner warp (w ^ 1)
    red[(w * 32 + lane) * 2]     = make_float4(s0_0, s1_0, a0_0, a1_0);
    red[(w * 32 + lane) * 2 + 1] = make_float4(s0_1, s1_1, a0_1, a1_1);
    __syncthreads();
    {
        const float4 o0 = red[((w ^ 1) * 32 + lane) * 2];
        const float4 o1 = red[((w ^ 1) * 32 + lane) * 2 + 1];
        s0_0 += o0.x; s1_0 += o0.y; a0_0 += o0.z; a1_0 += o0.w;
        s0_1 += o1.x; s1_1 += o1.y; a0_1 += o1.z; a1_1 += o1.w;
    }

    const float r0_0 = 1.0f / s0_0, r1_0 = 1.0f / s1_0;
    const float r0_1 = 1.0f / s0_1, r1_1 = 1.0f / s1_1;

    if (jh == 0) {
        const float h00 = a0_0 * r0_0, h10 = a1_0 * r1_0;
        const float h01 = a0_1 * r0_1, h11 = a1_1 * r1_1;
        float2 o0, o1;
        o0.x = (h00 > 0.0f) ? h00 : expm1f(h00);
        o0.y = (h10 > 0.0f) ? h10 : expm1f(h10);
        o1.x = (h01 > 0.0f) ? h01 : expm1f(h01);
        o1.y = (h11 > 0.0f) ? h11 : expm1f(h11);
        *(float2*)(out + ((size_t)t * V + i0) * F + f2) = o0;
        *(float2*)(out + ((size_t)t * V + i1) * F + f2) = o1;
    }

    // Pass B: prescaled products, stream normalized attention for both i's
    const float P0a = p1_0.x * r0_0, N0a = n1_0.x * r0_0;
    const float P0b = p1_0.y * r1_0, N0b = n1_0.y * r1_0;
    const float P1a = p1_1.x * r0_1, N1a = n1_1.x * r0_1;
    const float P1b = p1_1.y * r1_1, N1b = n1_1.y * r1_1;

    float* ab0 = out + ATT_OFF + (((size_t)t * V + i0) * V + jh * 64) * F + f2;
    float* ab1 = out + ATT_OFF + (((size_t)t * V + i1) * V + jh * 64) * F + f2;
#pragma unroll
    for (int ww = 0; ww < 2; ww++) {
        const uint32_t w0 = b0[ww], w1 = b1[ww];
        const uint32_t wa = w0 | w1;
        const float* pnw = pnl + ww * 32 * FH * 2;
        float* a0p = ab0 + (size_t)ww * 32 * F;
        float* a1p = ab1 + (size_t)ww * 32 * F;
#pragma unroll
        for (int b = 0; b < 32; b++) {
            float2 pv0 = {0.f, 0.f}, pv1 = {0.f, 0.f};
            if (wa & (1u << b)) {
                const float4 q = *(const float4*)(pnw + b * FH * 2);
                if (w0 & (1u << b)) {
                    pv0.x = fmaxf(P0a * q.x, N0a * q.y);
                    pv0.y = fmaxf(P0b * q.z, N0b * q.w);
                }
                if (w1 & (1u << b)) {
                    pv1.x = fmaxf(P1a * q.x, N1a * q.y);
                    pv1.y = fmaxf(P1b * q.z, N1b * q.w);
                }
            }
            __stcs((float2*)(a0p + b * F), pv0);
            __stcs((float2*)(a1p + b * F), pv1);
        }
    }
}

// ----------------------------------------------------------------------------
extern "C" void kernel_launch(void* const* d_in, const int* in_sizes, int n_in,
                              void* d_out, int out_size)
{
    const float* h   = (const float*)d_in[0];   // [2560,128]
    const float* adj = (const float*)d_in[1];   // [128,128,1]
    const float* W   = (const float*)d_in[2];   // [128,128]
    const float* a   = (const float*)d_in[3];   // [256,128]
    float* out = (float*)d_out;

    cudaFuncSetAttribute(attn_fused, cudaFuncAttributeMaxDynamicSharedMemorySize,
                         ATTN_SMEM_BYTES);

    gemm_fused<<<320, 256>>>(h, W, a);

    dim3 g2(16, NTIME);
    attn_fused<<<g2, 512, ATTN_SMEM_BYTES>>>(adj, out);
}

// round 13
// speedup vs baseline: 1.0825x; 1.0825x over previous
#include <cuda_runtime.h>
#include <cstdint>
#include <cstddef>
#include <cstring>

#define NTIME 20
#define V     128
#define F     128
#define LRELU_ALPHA 0.2f
#define LOG2E 1.4426950408889634f
#define ALOG2E (LRELU_ALPHA * LOG2E)

#define OUT_HP_ELEMS   (NTIME * V * F)
#define ATT_OFF        OUT_HP_ELEMS

__device__ float g_Wh[NTIME * V * F];
__device__ float g_P1[NTIME * V * F];      // exp2(log2e * e1)
__device__ float g_N1[NTIME * V * F];      // exp2(0.2 * log2e * e1)
__device__ float g_PN2[NTIME * V * F * 2]; // interleaved (exp2(l*e2), exp2(0.2l*e2))

__device__ __forceinline__ float ex2(float x) {
    float r; asm("ex2.approx.f32 %0, %1;" : "=f"(r) : "f"(x)); return r;
}

// ----------------------------------------------------------------------------
// Kernel 1 (fused): per block of MT=8 rows:
//   phase 1: Wh = h @ W        -> smem whs + g_Wh
//   phase 2: e1 = Whs @ a1, e2 = Whs @ a2  -> ex2 tables (P1/N1, PN2)
// 512 threads (f = tid&127, q = tid>>7 -> 2 rows/thread), grid = 320.
// Doubled warp count vs R11 to hide the LDG latency (R10: occ 35%, issue 27%).
// ----------------------------------------------------------------------------
#define MT 8

__global__ void __launch_bounds__(512) gemm_fused(
    const float* __restrict__ h,
    const float* __restrict__ W,
    const float* __restrict__ a)
{
    __shared__ float hs[MT * F];
    __shared__ float whs[MT * F];

    const int tid = threadIdx.x;
    const int f   = tid & 127;
    const int q   = tid >> 7;        // 0..3 -> rows q*2, q*2+1
    const int m0  = blockIdx.x * MT;

    if (tid < 256)
        ((float4*)hs)[tid] = ((const float4*)(h + (size_t)m0 * F))[tid];
    __syncthreads();

    // ---- phase 1: Wh ----
    {
        float acc[2] = {0.f, 0.f};
#pragma unroll 8
        for (int k4 = 0; k4 < F / 4; k4++) {
            float mv[4];
#pragma unroll
            for (int u = 0; u < 4; u++)
                mv[u] = __ldg(W + (k4 * 4 + u) * F + f);
#pragma unroll
            for (int r = 0; r < 2; r++) {
                const float4 hv = ((const float4*)(hs + (q * 2 + r) * F))[k4];
                acc[r] = fmaf(hv.x, mv[0], acc[r]);
                acc[r] = fmaf(hv.y, mv[1], acc[r]);
                acc[r] = fmaf(hv.z, mv[2], acc[r]);
                acc[r] = fmaf(hv.w, mv[3], acc[r]);
            }
        }
#pragma unroll
        for (int r = 0; r < 2; r++) {
            const int row = q * 2 + r;
            whs[row * F + f] = acc[r];
            g_Wh[(size_t)(m0 + row) * F + f] = acc[r];
        }
    }
    __syncthreads();

    // ---- phase 2: e1, e2 from whs ----
    {
        float ac1[2] = {0.f, 0.f};
        float ac2[2] = {0.f, 0.f};
#pragma unroll 8
        for (int k4 = 0; k4 < F / 4; k4++) {
            float a1v[4], a2v[4];
#pragma unroll
            for (int u = 0; u < 4; u++) {
                a1v[u] = __ldg(a + (k4 * 4 + u) * F + f);
                a2v[u] = __ldg(a + (F + k4 * 4 + u) * F + f);
            }
#pragma unroll
            for (int r = 0; r < 2; r++) {
                const float4 wv = ((const float4*)(whs + (q * 2 + r) * F))[k4];
                ac1[r] = fmaf(wv.x, a1v[0], ac1[r]);
                ac1[r] = fmaf(wv.y, a1v[1], ac1[r]);
                ac1[r] = fmaf(wv.z, a1v[2], ac1[r]);
                ac1[r] = fmaf(wv.w, a1v[3], ac1[r]);
                ac2[r] = fmaf(wv.x, a2v[0], ac2[r]);
                ac2[r] = fmaf(wv.y, a2v[1], ac2[r]);
                ac2[r] = fmaf(wv.z, a2v[2], ac2[r]);
                ac2[r] = fmaf(wv.w, a2v[3], ac2[r]);
            }
        }
#pragma unroll
        for (int r = 0; r < 2; r++) {
            const size_t idx = (size_t)(m0 + q * 2 + r) * F + f;
            g_P1[idx] = ex2(LOG2E  * ac1[r]);
            g_N1[idx] = ex2(ALOG2E * ac1[r]);
            *(float2*)(g_PN2 + idx * 2) =
                make_float2(ex2(LOG2E * ac2[r]), ex2(ALOG2E * ac2[r]));
        }
    }
}

// ----------------------------------------------------------------------------
// Kernel 2: attention (R11 structure — best measured — + fmaxf select):
//   p = max(P1*P2, N1*N2)   [== exp(leakyrelu(e1+e2)), since v>0 <=> P>=N]
// j-split: two warps per (i, f-half), each owning 64 j's; partials via smem.
// Block = 512 threads, grid = 32 x 20 = 640 (10240 warps), smem 72KB, 3 CTA/SM.
// ----------------------------------------------------------------------------
#define FH  64
#define IPB 8
#define ATTN_SMEM_BYTES ((2 * V * FH + 16 * 32 * 4) * (int)sizeof(float))

__global__ void __launch_bounds__(512, 3) attn_fused(
    const float* __restrict__ adj,
    float* __restrict__ out)
{
    extern __shared__ float sm[];
    float*  pn2 = sm;                        // [V][FH][2] = (P2,N2) interleaved
    float4* red = (float4*)(sm + 2 * V * FH);

    const int t    = blockIdx.y;
    const int bx   = blockIdx.x;      // 0..31
    const int fh   = bx & 1;
    const int ig   = bx >> 1;         // 0..15
    const int tid  = threadIdx.x;
    const int lane = tid & 31;
    const int w    = tid >> 5;        // warp 0..15
    const int il   = w >> 1;          // local i 0..7
    const int jh   = w & 1;           // j-half
    const int i    = ig * IPB + il;
    const int f2   = fh * FH + lane * 2;

    uint32_t bits[2];
    {
        const float* arow = adj + (size_t)i * V + jh * 64;
        bits[0] = __ballot_sync(0xFFFFFFFFu, arow[lane]      > 0.0f);
        bits[1] = __ballot_sync(0xFFFFFFFFu, arow[32 + lane] > 0.0f);
    }

    // coop load PN2 tile: 4096 float4, 8 per thread
    {
        const float* src = g_PN2 + ((size_t)t * V * F + fh * FH) * 2;
#pragma unroll
        for (int u = 0; u < 8; u++) {
            const int idx = tid + u * 512;
            const int j = idx >> 5, c = idx & 31;
            ((float4*)pn2)[idx] = *(const float4*)(src + (size_t)j * F * 2 + c * 4);
        }
    }

    const float2 p1 = *(const float2*)(g_P1 + ((size_t)t * V + i) * F + f2);
    const float2 n1 = *(const float2*)(g_N1 + ((size_t)t * V + i) * F + f2);
    __syncthreads();

    const float* pnl = pn2 + (jh * 64) * FH * 2 + lane * 4;
    const float* whg = g_Wh + ((size_t)t * V + jh * 64) * F + f2;

    // Pass A: partial sums over own 64 j's
    float s0 = 0.0f, s1 = 0.0f, a0 = 0.0f, a1 = 0.0f;
#pragma unroll
    for (int ww = 0; ww < 2; ww++) {
        const uint32_t bw = bits[ww];
        const float* pnw = pnl + ww * 32 * FH * 2;
        const float* whw = whg + (size_t)ww * 32 * F;
#pragma unroll
        for (int b = 0; b < 32; b++) {
            if (bw & (1u << b)) {
                const float4 q  = *(const float4*)(pnw + b * FH * 2);
                const float2 wv = __ldg((const float2*)(whw + (size_t)b * F));
                const float v0 = fmaxf(p1.x * q.x, n1.x * q.y);
                const float v1 = fmaxf(p1.y * q.z, n1.y * q.w);
                s0 += v0;  s1 += v1;
                a0 = fmaf(v0, wv.x, a0);
                a1 = fmaf(v1, wv.y, a1);
            }
        }
    }

    red[w * 32 + lane] = make_float4(s0, s1, a0, a1);
    __syncthreads();
    {
        const float4 o = red[(w ^ 1) * 32 + lane];
        s0 += o.x; s1 += o.y; a0 += o.z; a1 += o.w;
    }

    const float r0 = 1.0f / s0;
    const float r1 = 1.0f / s1;

    if (jh == 0) {
        const float hp0 = a0 * r0;
        const float hp1 = a1 * r1;
        float2 o;
        o.x = (hp0 > 0.0f) ? hp0 : expm1f(hp0);
        o.y = (hp1 > 0.0f) ? hp1 : expm1f(hp1);
        *(float2*)(out + ((size_t)t * V + i) * F + f2) = o;
    }

    // Pass B: prescaled products, stream normalized attention
    const float P1ra = p1.x * r0, N1ra = n1.x * r0;
    const float P1rb = p1.y * r1, N1rb = n1.y * r1;

    float* ab = out + ATT_OFF + (((size_t)t * V + i) * V + jh * 64) * F + f2;
#pragma unroll
    for (int ww = 0; ww < 2; ww++) {
        const uint32_t bw = bits[ww];
        const float* pnw = pnl + ww * 32 * FH * 2;
        float* abw = ab + (size_t)ww * 32 * F;
#pragma unroll
        for (int b = 0; b < 32; b++) {
            float2 pv;
            if (bw & (1u << b)) {
                const float4 q = *(const float4*)(pnw + b * FH * 2);
                pv.x = fmaxf(P1ra * q.x, N1ra * q.y);
                pv.y = fmaxf(P1rb * q.z, N1rb * q.w);
            } else {
                pv.x = 0.0f; pv.y = 0.0f;
            }
            __stcs((float2*)(abw + b * F), pv);
        }
    }
}

// ----------------------------------------------------------------------------
extern "C" void kernel_launch(void* const* d_in, const int* in_sizes, int n_in,
                              void* d_out, int out_size)
{
    const float* h   = (const float*)d_in[0];   // [2560,128]
    const float* adj = (const float*)d_in[1];   // [128,128,1]
    const float* W   = (const float*)d_in[2];   // [128,128]
    const float* a   = (const float*)d_in[3];   // [256,128]
    float* out = (float*)d_out;

    cudaFuncSetAttribute(attn_fused, cudaFuncAttributeMaxDynamicSharedMemorySize,
                         ATTN_SMEM_BYTES);

    gemm_fused<<<320, 512>>>(h, W, a);

    dim3 g2(32, NTIME);
    attn_fused<<<g2, 512, ATTN_SMEM_BYTES>>>(adj, out);
}

// round 14
// speedup vs baseline: 1.1657x; 1.0768x over previous
#include <cuda_runtime.h>
#include <cuda_fp16.h>
#include <cstdint>
#include <cstddef>
#include <cstring>

#define NTIME 20
#define V     128
#define F     128
#define LRELU_ALPHA 0.2f
#define LOG2E 1.4426950408889634f
#define ALOG2E (LRELU_ALPHA * LOG2E)

#define OUT_HP_ELEMS   (NTIME * V * F)
#define ATT_OFF        OUT_HP_ELEMS

__device__ float  g_Wh[NTIME * V * F];
__device__ float  g_P1[NTIME * V * F];        // exp2(log2e * e1)
__device__ float  g_N1[NTIME * V * F];        // exp2(0.2 * log2e * e1)
__device__ __half g_PN2[NTIME * V * F * 2];   // interleaved half (P2, N2) per f

__device__ __forceinline__ float ex2(float x) {
    float r; asm("ex2.approx.f32 %0, %1;" : "=f"(r) : "f"(x)); return r;
}

// ----------------------------------------------------------------------------
// Kernel 1 (fused, exact R11 shape): per block of MT=8 rows:
//   phase 1: Wh = h @ W        -> smem whs + g_Wh
//   phase 2: e1 = Whs @ a1, e2 = Whs @ a2  -> ex2 tables (P1/N1 fp32, PN2 half)
// 256 threads, 4 rows/thread, grid = 320.
// ----------------------------------------------------------------------------
#define MT 8

__global__ void __launch_bounds__(256) gemm_fused(
    const float* __restrict__ h,
    const float* __restrict__ W,
    const float* __restrict__ a)
{
    __shared__ float hs[MT * F];
    __shared__ float whs[MT * F];

    const int tid  = threadIdx.x;
    const int f    = tid & 127;
    const int half = tid >> 7;
    const int m0   = blockIdx.x * MT;

    ((float4*)hs)[tid] = ((const float4*)(h + (size_t)m0 * F))[tid];
    __syncthreads();

    {
        float acc[4] = {0.f, 0.f, 0.f, 0.f};
#pragma unroll 8
        for (int k4 = 0; k4 < F / 4; k4++) {
            float mv[4];
#pragma unroll
            for (int u = 0; u < 4; u++)
                mv[u] = __ldg(W + (k4 * 4 + u) * F + f);
#pragma unroll
            for (int r = 0; r < 4; r++) {
                const float4 hv = ((const float4*)(hs + (half * 4 + r) * F))[k4];
                acc[r] = fmaf(hv.x, mv[0], acc[r]);
                acc[r] = fmaf(hv.y, mv[1], acc[r]);
                acc[r] = fmaf(hv.z, mv[2], acc[r]);
                acc[r] = fmaf(hv.w, mv[3], acc[r]);
            }
        }
#pragma unroll
        for (int r = 0; r < 4; r++) {
            const int row = half * 4 + r;
            whs[row * F + f] = acc[r];
            g_Wh[(size_t)(m0 + row) * F + f] = acc[r];
        }
    }
    __syncthreads();

    {
        float ac1[4] = {0.f, 0.f, 0.f, 0.f};
        float ac2[4] = {0.f, 0.f, 0.f, 0.f};
#pragma unroll 8
        for (int k4 = 0; k4 < F / 4; k4++) {
            float a1v[4], a2v[4];
#pragma unroll
            for (int u = 0; u < 4; u++) {
                a1v[u] = __ldg(a + (k4 * 4 + u) * F + f);
                a2v[u] = __ldg(a + (F + k4 * 4 + u) * F + f);
            }
#pragma unroll
            for (int r = 0; r < 4; r++) {
                const float4 wv = ((const float4*)(whs + (half * 4 + r) * F))[k4];
                ac1[r] = fmaf(wv.x, a1v[0], ac1[r]);
                ac1[r] = fmaf(wv.y, a1v[1], ac1[r]);
                ac1[r] = fmaf(wv.z, a1v[2], ac1[r]);
                ac1[r] = fmaf(wv.w, a1v[3], ac1[r]);
                ac2[r] = fmaf(wv.x, a2v[0], ac2[r]);
                ac2[r] = fmaf(wv.y, a2v[1], ac2[r]);
                ac2[r] = fmaf(wv.z, a2v[2], ac2[r]);
                ac2[r] = fmaf(wv.w, a2v[3], ac2[r]);
            }
        }
#pragma unroll
        for (int r = 0; r < 4; r++) {
            const size_t idx = (size_t)(m0 + half * 4 + r) * F + f;
            g_P1[idx] = ex2(LOG2E  * ac1[r]);
            g_N1[idx] = ex2(ALOG2E * ac1[r]);
            const float P2 = ex2(LOG2E  * ac2[r]);
            const float N2 = ex2(ALOG2E * ac2[r]);
            *(__half2*)(g_PN2 + idx * 2) = __floats2half2_rn(P2, N2);
        }
    }
}

// ----------------------------------------------------------------------------
// Kernel 2: attention, R11 structure (best measured), PN2 tile in HALF:
//  - inner-loop tile access LDS.64 instead of LDS.128 (half the L1 wavefronts)
//  - tile staging 32KB instead of 64KB
//  - p = max(P1*P2, N1*N2)
// j-split: two warps per (i, f-half), each owning 64 j's; partials via smem.
// Block = 512 threads, grid = 32 x 20 = 640 (10240 warps), smem 40KB, 3 CTA/SM.
// ----------------------------------------------------------------------------
#define FH  64
#define IPB 8
#define ATTN_SMEM_BYTES (2 * V * FH * 2 + 16 * 32 * 16)   // 32KB tile + 8KB red

__global__ void __launch_bounds__(512, 3) attn_fused(
    const float* __restrict__ adj,
    float* __restrict__ out)
{
    extern __shared__ char smc[];
    __half* pn2 = (__half*)smc;                      // [V][FH][2] halves
    float4* red = (float4*)(smc + 2 * V * FH * 2);   // [16 warps][32 lanes]

    const int t    = blockIdx.y;
    const int bx   = blockIdx.x;      // 0..31
    const int fh   = bx & 1;
    const int ig   = bx >> 1;         // 0..15
    const int tid  = threadIdx.x;
    const int lane = tid & 31;
    const int w    = tid >> 5;        // warp 0..15
    const int il   = w >> 1;          // local i 0..7
    const int jh   = w & 1;           // j-half
    const int i    = ig * IPB + il;
    const int f2   = fh * FH + lane * 2;

    uint32_t bits[2];
    {
        const float* arow = adj + (size_t)i * V + jh * 64;
        bits[0] = __ballot_sync(0xFFFFFFFFu, arow[lane]      > 0.0f);
        bits[1] = __ballot_sync(0xFFFFFFFFu, arow[32 + lane] > 0.0f);
    }

    // coop load PN2 tile: 32KB = 2048 float4, 4 per thread
    {
        const __half* src = g_PN2 + ((size_t)t * V * F + fh * FH) * 2;
#pragma unroll
        for (int u = 0; u < 4; u++) {
            const int idx = tid + u * 512;          // 0..2047
            const int j = idx >> 4, c = idx & 15;   // 16 float4 per j-row
            ((float4*)pn2)[idx] = *(const float4*)(src + (size_t)j * F * 2 + c * 8);
        }
    }

    const float2 p1 = *(const float2*)(g_P1 + ((size_t)t * V + i) * F + f2);
    const float2 n1 = *(const float2*)(g_N1 + ((size_t)t * V + i) * F + f2);
    __syncthreads();

    const __half* pnl = pn2 + (jh * 64) * FH * 2 + lane * 4;
    const float*  whg = g_Wh + ((size_t)t * V + jh * 64) * F + f2;

    // Pass A: partial sums over own 64 j's
    float s0 = 0.0f, s1 = 0.0f, a0 = 0.0f, a1 = 0.0f;
#pragma unroll
    for (int ww = 0; ww < 2; ww++) {
        const uint32_t bw = bits[ww];
        const __half* pnw = pnl + ww * 32 * FH * 2;
        const float*  whw = whg + (size_t)ww * 32 * F;
#pragma unroll
        for (int b = 0; b < 32; b++) {
            if (bw & (1u << b)) {
                const uint2 qu = *(const uint2*)(pnw + b * FH * 2);
                const float2 q0 = __half22float2(*(const __half2*)&qu.x); // (P2,N2) f0
                const float2 q1 = __half22float2(*(const __half2*)&qu.y); // (P2,N2) f1
                const float2 wv = __ldg((const float2*)(whw + (size_t)b * F));
                const float v0 = fmaxf(p1.x * q0.x, n1.x * q0.y);
                const float v1 = fmaxf(p1.y * q1.x, n1.y * q1.y);
                s0 += v0;  s1 += v1;
                a0 = fmaf(v0, wv.x, a0);
                a1 = fmaf(v1, wv.y, a1);
            }
        }
    }

    red[w * 32 + lane] = make_float4(s0, s1, a0, a1);
    __syncthreads();
    {
        const float4 o = red[(w ^ 1) * 32 + lane];
        s0 += o.x; s1 += o.y; a0 += o.z; a1 += o.w;
    }

    const float r0 = 1.0f / s0;
    const float r1 = 1.0f / s1;

    if (jh == 0) {
        const float hp0 = a0 * r0;
        const float hp1 = a1 * r1;
        float2 o;
        o.x = (hp0 > 0.0f) ? hp0 : expm1f(hp0);
        o.y = (hp1 > 0.0f) ? hp1 : expm1f(hp1);
        *(float2*)(out + ((size_t)t * V + i) * F + f2) = o;
    }

    // Pass B: prescaled products, stream normalized attention
    const float P1ra = p1.x * r0, N1ra = n1.x * r0;
    const float P1rb = p1.y * r1, N1rb = n1.y * r1;

    float* ab = out + ATT_OFF + (((size_t)t * V + i) * V + jh * 64) * F + f2;
#pragma unroll
    for (int ww = 0; ww < 2; ww++) {
        const uint32_t bw = bits[ww];
        const __half* pnw = pnl + ww * 32 * FH * 2;
        float* abw = ab + (size_t)ww * 32 * F;
#pragma unroll
        for (int b = 0; b < 32; b++) {
            float2 pv;
            if (bw & (1u << b)) {
                const uint2 qu = *(const uint2*)(pnw + b * FH * 2);
                const float2 q0 = __half22float2(*(const __half2*)&qu.x);
                const float2 q1 = __half22float2(*(const __half2*)&qu.y);
                pv.x = fmaxf(P1ra * q0.x, N1ra * q0.y);
                pv.y = fmaxf(P1rb * q1.x, N1rb * q1.y);
            } else {
                pv.x = 0.0f; pv.y = 0.0f;
            }
            __stcs((float2*)(abw + b * F), pv);
        }
    }
}

// ----------------------------------------------------------------------------
extern "C" void kernel_launch(void* const* d_in, const int* in_sizes, int n_in,
                              void* d_out, int out_size)
{
    const float* h   = (const float*)d_in[0];   // [2560,128]
    const float* adj = (const float*)d_in[1];   // [128,128,1]
    const float* W   = (const float*)d_in[2];   // [128,128]
    const float* a   = (const float*)d_in[3];   // [256,128]
    float* out = (float*)d_out;

    cudaFuncSetAttribute(attn_fused, cudaFuncAttributeMaxDynamicSharedMemorySize,
                         ATTN_SMEM_BYTES);

    gemm_fused<<<320, 256>>>(h, W, a);

    dim3 g2(32, NTIME);
    attn_fused<<<g2, 512, ATTN_SMEM_BYTES>>>(adj, out);
}

// round 15
// speedup vs baseline: 1.2449x; 1.0679x over previous
#include <cuda_runtime.h>
#include <cuda_fp16.h>
#include <cstdint>
#include <cstddef>
#include <cstring>

#define NTIME 20
#define V     128
#define F     128
#define LRELU_ALPHA 0.2f
#define LOG2E 1.4426950408889634f
#define ALOG2E (LRELU_ALPHA * LOG2E)

#define OUT_HP_ELEMS   (NTIME * V * F)
#define ATT_OFF        OUT_HP_ELEMS

__device__ __half g_Whh[NTIME * V * F];       // Wh in half (only used for h_prime)
__device__ float  g_P1[NTIME * V * F];        // exp2(log2e * e1)
__device__ float  g_N1[NTIME * V * F];        // exp2(0.2 * log2e * e1)
__device__ __half g_PN2[NTIME * V * F * 2];   // interleaved half (P2, N2) per f

__device__ __forceinline__ float ex2(float x) {
    float r; asm("ex2.approx.f32 %0, %1;" : "=f"(r) : "f"(x)); return r;
}

// ----------------------------------------------------------------------------
// Kernel 1 (fused): per block of MT=4 rows (grid 640 -> 2x warps vs R14):
//   phase 1: Wh = h @ W        -> smem whs (fp32) + g_Whh (half)
//   phase 2: e1 = Whs @ a1, e2 = Whs @ a2  -> ex2 tables (P1/N1 fp32, PN2 half)
// 256 threads: f = tid&127, half = tid>>7, 2 rows/thread.
// ----------------------------------------------------------------------------
#define MT 4

__global__ void __launch_bounds__(256) gemm_fused(
    const float* __restrict__ h,
    const float* __restrict__ W,
    const float* __restrict__ a)
{
    __shared__ float hs[MT * F];
    __shared__ float whs[MT * F];

    const int tid = threadIdx.x;
    const int f   = tid & 127;
    const int hf  = tid >> 7;
    const int m0  = blockIdx.x * MT;

    if (tid < 128)
        ((float4*)hs)[tid] = ((const float4*)(h + (size_t)m0 * F))[tid];
    __syncthreads();

    // ---- phase 1: Wh ----
    {
        float acc[2] = {0.f, 0.f};
#pragma unroll 8
        for (int k4 = 0; k4 < F / 4; k4++) {
            float mv[4];
#pragma unroll
            for (int u = 0; u < 4; u++)
                mv[u] = __ldg(W + (k4 * 4 + u) * F + f);
#pragma unroll
            for (int r = 0; r < 2; r++) {
                const float4 hv = ((const float4*)(hs + (hf * 2 + r) * F))[k4];
                acc[r] = fmaf(hv.x, mv[0], acc[r]);
                acc[r] = fmaf(hv.y, mv[1], acc[r]);
                acc[r] = fmaf(hv.z, mv[2], acc[r]);
                acc[r] = fmaf(hv.w, mv[3], acc[r]);
            }
        }
#pragma unroll
        for (int r = 0; r < 2; r++) {
            const int row = hf * 2 + r;
            whs[row * F + f] = acc[r];
            g_Whh[(size_t)(m0 + row) * F + f] = __float2half_rn(acc[r]);
        }
    }
    __syncthreads();

    // ---- phase 2: e1, e2 from whs ----
    {
        float ac1[2] = {0.f, 0.f};
        float ac2[2] = {0.f, 0.f};
#pragma unroll 8
        for (int k4 = 0; k4 < F / 4; k4++) {
            float a1v[4], a2v[4];
#pragma unroll
            for (int u = 0; u < 4; u++) {
                a1v[u] = __ldg(a + (k4 * 4 + u) * F + f);
                a2v[u] = __ldg(a + (F + k4 * 4 + u) * F + f);
            }
#pragma unroll
            for (int r = 0; r < 2; r++) {
                const float4 wv = ((const float4*)(whs + (hf * 2 + r) * F))[k4];
                ac1[r] = fmaf(wv.x, a1v[0], ac1[r]);
                ac1[r] = fmaf(wv.y, a1v[1], ac1[r]);
                ac1[r] = fmaf(wv.z, a1v[2], ac1[r]);
                ac1[r] = fmaf(wv.w, a1v[3], ac1[r]);
                ac2[r] = fmaf(wv.x, a2v[0], ac2[r]);
                ac2[r] = fmaf(wv.y, a2v[1], ac2[r]);
                ac2[r] = fmaf(wv.z, a2v[2], ac2[r]);
                ac2[r] = fmaf(wv.w, a2v[3], ac2[r]);
            }
        }
#pragma unroll
        for (int r = 0; r < 2; r++) {
            const size_t idx = (size_t)(m0 + hf * 2 + r) * F + f;
            g_P1[idx] = ex2(LOG2E  * ac1[r]);
            g_N1[idx] = ex2(ALOG2E * ac1[r]);
            const float P2 = ex2(LOG2E  * ac2[r]);
            const float N2 = ex2(ALOG2E * ac2[r]);
            *(__half2*)(g_PN2 + idx * 2) = __floats2half2_rn(P2, N2);
        }
    }
}

// ----------------------------------------------------------------------------
// Kernel 2: attention. R14 structure + Wh tile in smem (half):
//  - pass A per j: LDS.64 (PN2) + LDS.32 (Wh half2); NO global loads in loop
//  - p = max(P1*P2, N1*N2)
// j-split: two warps per (i, f-half), each owning 64 j's; partials via smem.
// Block = 512 threads, grid = 32 x 20 = 640 (10240 warps).
// smem = PN2 32KB + Wh 16KB + red 8KB = 56KB -> 3 CTA/SM.
// ----------------------------------------------------------------------------
#define FH  64
#define IPB 8
#define ATTN_SMEM_BYTES (2 * V * FH * 2 + V * FH * 2 + 16 * 32 * 16)

__global__ void __launch_bounds__(512, 3) attn_fused(
    const float* __restrict__ adj,
    float* __restrict__ out)
{
    extern __shared__ char smc[];
    __half* pn2 = (__half*)smc;                            // [V][FH][2]
    __half* whs = (__half*)(smc + 2 * V * FH * 2);         // [V][FH]
    float4* red = (float4*)(smc + 3 * V * FH * 2);         // [16][32]

    const int t    = blockIdx.y;
    const int bx   = blockIdx.x;      // 0..31
    const int fh   = bx & 1;
    const int ig   = bx >> 1;         // 0..15
    const int tid  = threadIdx.x;
    const int lane = tid & 31;
    const int w    = tid >> 5;        // warp 0..15
    const int il   = w >> 1;          // local i 0..7
    const int jh   = w & 1;           // j-half
    const int i    = ig * IPB + il;
    const int f2   = fh * FH + lane * 2;

    uint32_t bits[2];
    {
        const float* arow = adj + (size_t)i * V + jh * 64;
        bits[0] = __ballot_sync(0xFFFFFFFFu, arow[lane]      > 0.0f);
        bits[1] = __ballot_sync(0xFFFFFFFFu, arow[32 + lane] > 0.0f);
    }

    // coop load PN2 tile (2048 float4, 4/thread) + Wh half tile (1024 float4, 2/thread)
    {
        const __half* src = g_PN2 + ((size_t)t * V * F + fh * FH) * 2;
#pragma unroll
        for (int u = 0; u < 4; u++) {
            const int idx = tid + u * 512;          // 0..2047
            const int j = idx >> 4, c = idx & 15;   // 16 float4 per j-row
            ((float4*)pn2)[idx] = *(const float4*)(src + (size_t)j * F * 2 + c * 8);
        }
        const __half* wsrc = g_Whh + (size_t)t * V * F + fh * FH;
#pragma unroll
        for (int u = 0; u < 2; u++) {
            const int idx = tid + u * 512;          // 0..1023
            const int j = idx >> 3, c = idx & 7;    // 8 float4 per j-row
            ((float4*)whs)[idx] = *(const float4*)(wsrc + (size_t)j * F + c * 8);
        }
    }

    const float2 p1 = *(const float2*)(g_P1 + ((size_t)t * V + i) * F + f2);
    const float2 n1 = *(const float2*)(g_N1 + ((size_t)t * V + i) * F + f2);
    __syncthreads();

    const __half* pnl = pn2 + (jh * 64) * FH * 2 + lane * 4;
    const __half* whl = whs + (jh * 64) * FH + lane * 2;

    // Pass A: partial sums over own 64 j's (all shared-memory)
    float s0 = 0.0f, s1 = 0.0f, a0 = 0.0f, a1 = 0.0f;
#pragma unroll
    for (int ww = 0; ww < 2; ww++) {
        const uint32_t bw = bits[ww];
        const __half* pnw = pnl + ww * 32 * FH * 2;
        const __half* whw = whl + ww * 32 * FH;
#pragma unroll
        for (int b = 0; b < 32; b++) {
            if (bw & (1u << b)) {
                const uint2 qu = *(const uint2*)(pnw + b * FH * 2);
                const float2 q0 = __half22float2(*(const __half2*)&qu.x);
                const float2 q1 = __half22float2(*(const __half2*)&qu.y);
                const float2 wv = __half22float2(*(const __half2*)(whw + b * FH));
                const float v0 = fmaxf(p1.x * q0.x, n1.x * q0.y);
                const float v1 = fmaxf(p1.y * q1.x, n1.y * q1.y);
                s0 += v0;  s1 += v1;
                a0 = fmaf(v0, wv.x, a0);
                a1 = fmaf(v1, wv.y, a1);
            }
        }
    }

    red[w * 32 + lane] = make_float4(s0, s1, a0, a1);
    __syncthreads();
    {
        const float4 o = red[(w ^ 1) * 32 + lane];
        s0 += o.x; s1 += o.y; a0 += o.z; a1 += o.w;
    }

    const float r0 = 1.0f / s0;
    const float r1 = 1.0f / s1;

    if (jh == 0) {
        const float hp0 = a0 * r0;
        const float hp1 = a1 * r1;
        float2 o;
        o.x = (hp0 > 0.0f) ? hp0 : expm1f(hp0);
        o.y = (hp1 > 0.0f) ? hp1 : expm1f(hp1);
        *(float2*)(out + ((size_t)t * V + i) * F + f2) = o;
    }

    // Pass B: prescaled products, stream normalized attention
    const float P1ra = p1.x * r0, N1ra = n1.x * r0;
    const float P1rb = p1.y * r1, N1rb = n1.y * r1;

    float* ab = out + ATT_OFF + (((size_t)t * V + i) * V + jh * 64) * F + f2;
#pragma unroll
    for (int ww = 0; ww < 2; ww++) {
        const uint32_t bw = bits[ww];
        const __half* pnw = pnl + ww * 32 * FH * 2;
        float* abw = ab + (size_t)ww * 32 * F;
#pragma unroll
        for (int b = 0; b < 32; b++) {
            float2 pv;
            if (bw & (1u << b)) {
                const uint2 qu = *(const uint2*)(pnw + b * FH * 2);
                const float2 q0 = __half22float2(*(const __half2*)&qu.x);
                const float2 q1 = __half22float2(*(const __half2*)&qu.y);
                pv.x = fmaxf(P1ra * q0.x, N1ra * q0.y);
                pv.y = fmaxf(P1rb * q1.x, N1rb * q1.y);
            } else {
                pv.x = 0.0f; pv.y = 0.0f;
            }
            __stcs((float2*)(abw + b * F), pv);
        }
    }
}

// ----------------------------------------------------------------------------
extern "C" void kernel_launch(void* const* d_in, const int* in_sizes, int n_in,
                              void* d_out, int out_size)
{
    const float* h   = (const float*)d_in[0];   // [2560,128]
    const float* adj = (const float*)d_in[1];   // [128,128,1]
    const float* W   = (const float*)d_in[2];   // [128,128]
    const float* a   = (const float*)d_in[3];   // [256,128]
    float* out = (float*)d_out;

    cudaFuncSetAttribute(attn_fused, cudaFuncAttributeMaxDynamicSharedMemorySize,
                         ATTN_SMEM_BYTES);

    gemm_fused<<<640, 256>>>(h, W, a);

    dim3 g2(32, NTIME);
    attn_fused<<<g2, 512, ATTN_SMEM_BYTES>>>(adj, out);
}